// round 8
// baseline (speedup 1.0000x reference)
#include <cuda_runtime.h>
#include <cuda_fp16.h>
#include <cstdint>

#define B_   32
#define C_   256
#define H_   128
#define W_   128
#define R_   128
#define F_   256
#define HP   126
#define WP   126
#define WPAD 128
#define HW_  (H_ * W_)

// ---- device scratch (allocation-free) -----------------------------------
__device__ __half g_yh[(size_t)B_ * R_ * H_ * W_];     // fp16 134 MB
__device__ __half g_zh[(size_t)B_ * R_ * HP * WPAD];   // fp16 132 MB
__device__ __half g_f3h[128 * 256];                    // f3^T [r][c]
__device__ __half g_f0h[256 * 128];                    // f0   [f][r]

// ---- PTX helpers --------------------------------------------------------
__device__ __forceinline__ uint32_t smem_u32(const void* p) {
    uint32_t a;
    asm("{ .reg .u64 t; cvta.to.shared.u64 t, %1; cvt.u32.u64 %0, t; }"
        : "=r"(a) : "l"(p));
    return a;
}
__device__ __forceinline__ void ldsm_x4(uint32_t* r, uint32_t addr) {
    asm volatile("ldmatrix.sync.aligned.m8n8.x4.shared.b16 {%0,%1,%2,%3}, [%4];"
                 : "=r"(r[0]), "=r"(r[1]), "=r"(r[2]), "=r"(r[3]) : "r"(addr));
}
__device__ __forceinline__ void ldsm_x4t(uint32_t* r, uint32_t addr) {
    asm volatile("ldmatrix.sync.aligned.m8n8.x4.trans.shared.b16 {%0,%1,%2,%3}, [%4];"
                 : "=r"(r[0]), "=r"(r[1]), "=r"(r[2]), "=r"(r[3]) : "r"(addr));
}
__device__ __forceinline__ void mma16816(float* c, const uint32_t* a,
                                         const uint32_t* b) {
    asm volatile(
        "mma.sync.aligned.m16n8k16.row.col.f32.f16.f16.f32 "
        "{%0,%1,%2,%3}, {%4,%5,%6,%7}, {%8,%9}, {%0,%1,%2,%3};"
        : "+f"(c[0]), "+f"(c[1]), "+f"(c[2]), "+f"(c[3])
        : "r"(a[0]), "r"(a[1]), "r"(a[2]), "r"(a[3]), "r"(b[0]), "r"(b[1]));
}
__device__ __forceinline__ void cp_async16(uint32_t dst, const void* src) {
    asm volatile("{ .reg .u64 g; cvta.to.global.u64 g, %1;"
                 "  cp.async.cg.shared.global [%0], [g], 16; }"
                 :: "r"(dst), "l"(src) : "memory");
}
#define CP_COMMIT() asm volatile("cp.async.commit_group;" ::: "memory")
#define CP_WAIT(n)  asm volatile("cp.async.wait_group %0;" :: "n"(n) : "memory")

#define A_LD  24    // halves per A smem row (16 + 8 pad) -> 48B stride
#define B3_LD 136   // K3 B row: 128 + 8 pad halves
#define B1_LD 264   // K1 B row: 256 + 8 pad halves

// =========================================================================
// Setup: f0 -> fp16 [f][r] ; f3 transpose -> fp16 [r][c]
// =========================================================================
__global__ void ksplit_weights(const float* __restrict__ f0,
                               const float* __restrict__ f3) {
    int i = blockIdx.x * 256 + threadIdx.x;
    if (i < 256 * 128) g_f0h[i] = __float2half_rn(f0[i]);
    if (i < 128 * 256) {
        int m = i >> 8, k = i & 255;
        g_f3h[m * 256 + k] = __float2half_rn(f3[k * 128 + m]);
    }
}

// =========================================================================
// K1: y[b,r,h,w] = sum_c f3t[r,c] x[b,c,h,w]   (y fp16)
// block: M=128 (r), N=256 (2 h-rows, contiguous in x), K=256, chunks of 16
// 512 threads, warps 4m x 4n, warp tile 32x64, 2-stage reg prefetch
// =========================================================================
__global__ __launch_bounds__(512, 1)
void k1_mma(const float* __restrict__ x) {
    __shared__ __half As[2][128 * A_LD];
    __shared__ __half Bs[2][16 * B1_LD];

    const int tid = threadIdx.x, wid = tid >> 5, lane = tid & 31;
    const int b = blockIdx.y, h0 = blockIdx.x * 2;
    const int wm = wid & 3, wn = wid >> 2;
    const float* xb = x + ((size_t)b * C_) * HW_ + (size_t)h0 * W_;

    float acc[2][8][4];
#pragma unroll
    for (int i = 0; i < 2; ++i)
#pragma unroll
        for (int j = 0; j < 8; ++j)
#pragma unroll
            for (int q = 0; q < 4; ++q) acc[i][j][q] = 0.f;

    const int am = tid >> 1, akh = (tid & 1) * 8;   // A loader (tid<256)
    const int bk = tid >> 5, bn8 = (tid & 31) * 8;  // B loader (all 512)

    // preload chunk 0
    {
        if (tid < 256)
            *(uint4*)&As[0][am * A_LD + akh] = *(const uint4*)&g_f3h[am * 256 + akh];
        float4 v0 = *(const float4*)(xb + (size_t)bk * HW_ + bn8);
        float4 v1 = *(const float4*)(xb + (size_t)bk * HW_ + bn8 + 4);
        __half2 p0 = __floats2half2_rn(v0.x, v0.y), p1 = __floats2half2_rn(v0.z, v0.w);
        __half2 p2 = __floats2half2_rn(v1.x, v1.y), p3 = __floats2half2_rn(v1.z, v1.w);
        uint4 w = make_uint4(*(uint32_t*)&p0, *(uint32_t*)&p1,
                             *(uint32_t*)&p2, *(uint32_t*)&p3);
        *(uint4*)&Bs[0][bk * B1_LD + bn8] = w;
    }
    __syncthreads();

    const uint32_t aBase = smem_u32(&As[0][0]);
    const uint32_t bBase = smem_u32(&Bs[0][0]);
    const int arow = wm * 32 + (lane & 15);
    const int acol = (lane >> 4) * 8;
    const int brow = (lane & 7) + ((lane >> 3) & 1) * 8;
    const int bcol = wn * 64 + ((lane >> 4) & 1) * 8;

    int cur = 0;
#pragma unroll 1
    for (int kc = 0; kc < 16; ++kc) {
        uint4 pa; float4 pb0, pb1;
        const bool more = (kc + 1) < 16;
        if (more) {
            int c0n = (kc + 1) * 16;
            if (tid < 256) pa = *(const uint4*)&g_f3h[am * 256 + c0n + akh];
            pb0 = *(const float4*)(xb + (size_t)(c0n + bk) * HW_ + bn8);
            pb1 = *(const float4*)(xb + (size_t)(c0n + bk) * HW_ + bn8 + 4);
        }

        uint32_t a[2][4];
        const uint32_t aS = aBase + cur * (128 * A_LD * 2);
#pragma unroll
        for (int mf = 0; mf < 2; ++mf)
            ldsm_x4(a[mf], aS + ((arow + mf * 16) * A_LD + acol) * 2);
        const uint32_t bS = bBase + cur * (16 * B1_LD * 2);
#pragma unroll
        for (int g = 0; g < 4; ++g) {
            uint32_t bf[4];
            ldsm_x4t(bf, bS + (brow * B1_LD + bcol + g * 16) * 2);
#pragma unroll
            for (int mf = 0; mf < 2; ++mf) {
                mma16816(acc[mf][g * 2 + 0], a[mf], bf + 0);
                mma16816(acc[mf][g * 2 + 1], a[mf], bf + 2);
            }
        }

        if (more) {
            int nxt = cur ^ 1;
            if (tid < 256) *(uint4*)&As[nxt][am * A_LD + akh] = pa;
            __half2 p0 = __floats2half2_rn(pb0.x, pb0.y), p1 = __floats2half2_rn(pb0.z, pb0.w);
            __half2 p2 = __floats2half2_rn(pb1.x, pb1.y), p3 = __floats2half2_rn(pb1.z, pb1.w);
            uint4 w = make_uint4(*(uint32_t*)&p0, *(uint32_t*)&p1,
                                 *(uint32_t*)&p2, *(uint32_t*)&p3);
            *(uint4*)&Bs[nxt][bk * B1_LD + bn8] = w;
            __syncthreads();
            cur = nxt;
        }
    }

    // epilogue: y fp16; n -> (h = h0 + n>>7, w = n&127); rows contiguous
    const int r0 = wm * 32, n0 = wn * 64;
    const int lr = lane >> 2, lc = (lane & 3) * 2;
#pragma unroll
    for (int mf = 0; mf < 2; ++mf)
#pragma unroll
        for (int g = 0; g < 8; ++g) {
            int r = r0 + mf * 16 + lr;
            int n = n0 + g * 8 + lc;
            __half2 v0 = __floats2half2_rn(acc[mf][g][0], acc[mf][g][1]);
            __half2 v1 = __floats2half2_rn(acc[mf][g][2], acc[mf][g][3]);
            // y[b][r][h0][0..] : two h rows are contiguous -> flat offset n
            *(__half2*)(g_yh + (((size_t)b * R_ + r) * H_ + h0) * W_ + n) = v0;
            *(__half2*)(g_yh + (((size_t)b * R_ + r + 8) * H_ + h0) * W_ + n) = v1;
        }
}

// =========================================================================
// K2: separable depthwise, y fp16 -> z fp16, 8 outputs/thread, 16B stores
// =========================================================================
__global__ __launch_bounds__(256)
void k2_depthwise(const float* __restrict__ f1, const float* __restrict__ f2) {
    const int tid = threadIdx.x;
    const int qi = tid & 15, psub = tid >> 4;
    const int p = blockIdx.x * 16 + psub;
    const int r = blockIdx.y, b = blockIdx.z;
    if (p >= HP) return;

    const float w0 = f2[r], w1 = f2[128 + r], w2 = f2[256 + r];
    const float v0 = f1[r], v1 = f1[128 + r], v2 = f1[256 + r];

    const __half* yb = g_yh + ((((size_t)b * R_) + r) * H_ + p) * W_;
    const int q0 = qi * 8;

    float z[8];
#pragma unroll
    for (int j = 0; j < 8; ++j) z[j] = 0.f;

#pragma unroll
    for (int a = 0; a < 3; ++a) {
        const __half* row = yb + a * W_ + q0;
        float t[10];
        uint4 raw = *(const uint4*)row;          // 8 halves
        __half2* hp = (__half2*)&raw;
#pragma unroll
        for (int j = 0; j < 4; ++j) {
            float2 f = __half22float2(hp[j]);
            t[j * 2] = f.x; t[j * 2 + 1] = f.y;
        }
        if (q0 < 120) {
            float2 f = __half22float2(*(const __half2*)(row + 8));
            t[8] = f.x; t[9] = f.y;
        } else { t[8] = 0.f; t[9] = 0.f; }
        const float va = (a == 0) ? v0 : ((a == 1) ? v1 : v2);
#pragma unroll
        for (int j = 0; j < 8; ++j)
            z[j] += va * (t[j] * w0 + t[j + 1] * w1 + t[j + 2] * w2);
    }
    if (q0 == 120) { z[6] = 0.f; z[7] = 0.f; }

    __half2 o0 = __floats2half2_rn(z[0], z[1]), o1 = __floats2half2_rn(z[2], z[3]);
    __half2 o2 = __floats2half2_rn(z[4], z[5]), o3 = __floats2half2_rn(z[6], z[7]);
    uint4 w = make_uint4(*(uint32_t*)&o0, *(uint32_t*)&o1,
                         *(uint32_t*)&o2, *(uint32_t*)&o3);
    *(uint4*)(g_zh + ((((size_t)b * R_) + r) * HP + p) * WPAD + q0) = w;
}

// =========================================================================
// K3: out[b,f,p,q] = sum_r f0[f,r] z[b,r,p,q]
// block: M=256 (all f), N=128 (q padded), K=128, chunks of 16
// 512 threads, warps 8m x 2n, warp tile 32x64, 4-stage cp.async, dyn smem
// =========================================================================
#define K3_ASZ (256 * A_LD)          // halves per A stage
#define K3_BSZ (16 * B3_LD)          // halves per B stage
#define K3_SMEM ((4 * K3_ASZ + 4 * K3_BSZ) * 2)

__global__ __launch_bounds__(512, 1)
void k3_mma(float* __restrict__ out) {
    extern __shared__ __half sm3[];
    __half* Asm = sm3;               // 4 stages of A
    __half* Bsm = sm3 + 4 * K3_ASZ;  // 4 stages of B

    const int tid = threadIdx.x, wid = tid >> 5, lane = tid & 31;
    const int p = blockIdx.x, b = blockIdx.y;
    const int wm = wid & 7, wn = wid >> 3;
    const __half* zb = g_zh + ((size_t)b * R_ * HP + p) * WPAD;
    const size_t zks = (size_t)HP * WPAD;

    float acc[2][8][4];
#pragma unroll
    for (int i = 0; i < 2; ++i)
#pragma unroll
        for (int j = 0; j < 8; ++j)
#pragma unroll
            for (int q = 0; q < 4; ++q) acc[i][j][q] = 0.f;

    const int ar = tid >> 1, asg = (tid & 1) * 8;   // A: 512 segs, 1/thread
    const int br = tid >> 4, bsg = (tid & 15) * 8;  // B: 256 segs, tid<256

#define K3_ISSUE(kc, st)                                                      \
    do {                                                                      \
        int k0_ = (kc) * 16;                                                  \
        cp_async16(smem_u32(&Asm[(st) * K3_ASZ + ar * A_LD + asg]),           \
                   g_f0h + (size_t)ar * 128 + k0_ + asg);                     \
        if (tid < 256)                                                        \
            cp_async16(smem_u32(&Bsm[(st) * K3_BSZ + br * B3_LD + bsg]),      \
                       zb + (size_t)(k0_ + br) * zks + bsg);                  \
        CP_COMMIT();                                                          \
    } while (0)

    K3_ISSUE(0, 0);
    K3_ISSUE(1, 1);
    K3_ISSUE(2, 2);

    const uint32_t aBase = smem_u32(&Asm[0]);
    const uint32_t bBase = smem_u32(&Bsm[0]);
    const int arow = wm * 32 + (lane & 15);
    const int acol = (lane >> 4) * 8;
    const int brow = (lane & 7) + ((lane >> 3) & 1) * 8;
    const int bcol = wn * 64 + ((lane >> 4) & 1) * 8;

#pragma unroll 1
    for (int kc = 0; kc < 8; ++kc) {
        if (kc < 6) CP_WAIT(2); else CP_WAIT(0);
        __syncthreads();
        if (kc + 3 < 8) K3_ISSUE(kc + 3, (kc + 3) & 3);

        const int s = kc & 3;
        uint32_t a[2][4];
        const uint32_t aS = aBase + s * (K3_ASZ * 2);
#pragma unroll
        for (int mf = 0; mf < 2; ++mf)
            ldsm_x4(a[mf], aS + ((arow + mf * 16) * A_LD + acol) * 2);
        const uint32_t bS = bBase + s * (K3_BSZ * 2);
#pragma unroll
        for (int g = 0; g < 4; ++g) {
            uint32_t bf[4];
            ldsm_x4t(bf, bS + (brow * B3_LD + bcol + g * 16) * 2);
#pragma unroll
            for (int mf = 0; mf < 2; ++mf) {
                mma16816(acc[mf][g * 2 + 0], a[mf], bf + 0);
                mma16816(acc[mf][g * 2 + 1], a[mf], bf + 2);
            }
        }
    }

    // epilogue: out[b][f][p][q], skip q >= 126
    const int r0 = wm * 32, n0 = wn * 64;
    const int lr = lane >> 2, lc = (lane & 3) * 2;
#pragma unroll
    for (int mf = 0; mf < 2; ++mf)
#pragma unroll
        for (int g = 0; g < 8; ++g) {
            int f = r0 + mf * 16 + lr;
            int q = n0 + g * 8 + lc;
            if (q < WP) {
                float* d0 = out + (((size_t)(b * F_ + f)) * HP + p) * WP + q;
                *(float2*)d0 = make_float2(acc[mf][g][0], acc[mf][g][1]);
                float* d1 = out + (((size_t)(b * F_ + f + 8)) * HP + p) * WP + q;
                *(float2*)d1 = make_float2(acc[mf][g][2], acc[mf][g][3]);
            }
        }
}

extern "C" void kernel_launch(void* const* d_in, const int* in_sizes, int n_in,
                              void* d_out, int out_size) {
    const float* x  = (const float*)d_in[0];
    const float* f0 = (const float*)d_in[1];
    const float* f1 = (const float*)d_in[2];
    const float* f2 = (const float*)d_in[3];
    const float* f3 = (const float*)d_in[4];
    float* out = (float*)d_out;

    static int smem_set = 0;
    if (!smem_set) {
        cudaFuncSetAttribute(k3_mma, cudaFuncAttributeMaxDynamicSharedMemorySize,
                             K3_SMEM);
        smem_set = 1;
    }

    ksplit_weights<<<128, 256>>>(f0, f3);
    k1_mma<<<dim3(H_ / 2, B_), 512>>>(x);
    k2_depthwise<<<dim3(8, R_, B_), 256>>>(f1, f2);
    k3_mma<<<dim3(HP, B_), 512, K3_SMEM>>>(out);
}

// round 9
// speedup vs baseline: 1.0635x; 1.0635x over previous
#include <cuda_runtime.h>
#include <cuda_fp16.h>
#include <cstdint>

#define B_   32
#define C_   256
#define H_   128
#define W_   128
#define R_   128
#define F_   256
#define HP   126
#define WP   126
#define WPAD 128
#define HW_  (H_ * W_)

// ---- device scratch (allocation-free) -----------------------------------
__device__ __half g_yh[(size_t)B_ * R_ * H_ * W_];     // fp16 134 MB
__device__ __half g_zh[(size_t)B_ * R_ * HP * WPAD];   // fp16 132 MB
__device__ __half g_f3h[128 * 256];                    // f3^T [r][c]
__device__ __half g_f0h[256 * 128];                    // f0   [f][r]

// ---- PTX helpers --------------------------------------------------------
__device__ __forceinline__ uint32_t smem_u32(const void* p) {
    uint32_t a;
    asm("{ .reg .u64 t; cvta.to.shared.u64 t, %1; cvt.u32.u64 %0, t; }"
        : "=r"(a) : "l"(p));
    return a;
}
__device__ __forceinline__ void ldsm_x4(uint32_t* r, uint32_t addr) {
    asm volatile("ldmatrix.sync.aligned.m8n8.x4.shared.b16 {%0,%1,%2,%3}, [%4];"
                 : "=r"(r[0]), "=r"(r[1]), "=r"(r[2]), "=r"(r[3]) : "r"(addr));
}
__device__ __forceinline__ void ldsm_x4t(uint32_t* r, uint32_t addr) {
    asm volatile("ldmatrix.sync.aligned.m8n8.x4.trans.shared.b16 {%0,%1,%2,%3}, [%4];"
                 : "=r"(r[0]), "=r"(r[1]), "=r"(r[2]), "=r"(r[3]) : "r"(addr));
}
__device__ __forceinline__ void mma16816(float* c, const uint32_t* a,
                                         const uint32_t* b) {
    asm volatile(
        "mma.sync.aligned.m16n8k16.row.col.f32.f16.f16.f32 "
        "{%0,%1,%2,%3}, {%4,%5,%6,%7}, {%8,%9}, {%0,%1,%2,%3};"
        : "+f"(c[0]), "+f"(c[1]), "+f"(c[2]), "+f"(c[3])
        : "r"(a[0]), "r"(a[1]), "r"(a[2]), "r"(a[3]), "r"(b[0]), "r"(b[1]));
}
__device__ __forceinline__ void cp_async16(uint32_t dst, const void* src) {
    asm volatile("{ .reg .u64 g; cvta.to.global.u64 g, %1;"
                 "  cp.async.cg.shared.global [%0], [g], 16; }"
                 :: "r"(dst), "l"(src) : "memory");
}
#define CP_COMMIT() asm volatile("cp.async.commit_group;" ::: "memory")
#define CP_WAIT(n)  asm volatile("cp.async.wait_group %0;" :: "n"(n) : "memory")

#define A_LD  24    // halves per A smem row (16 + 8 pad) -> 48B stride
#define B3_LD 136   // K3 B row: 128 + 8 pad halves
#define B1_LD 264   // K1 B row: 256 + 8 pad halves

// =========================================================================
// Setup: f0 -> fp16 [f][r] ; f3 transpose -> fp16 [r][c]
// =========================================================================
__global__ void ksplit_weights(const float* __restrict__ f0,
                               const float* __restrict__ f3) {
    int i = blockIdx.x * 256 + threadIdx.x;
    if (i < 256 * 128) g_f0h[i] = __float2half_rn(f0[i]);
    if (i < 128 * 256) {
        int m = i >> 8, k = i & 255;
        g_f3h[m * 256 + k] = __float2half_rn(f3[k * 128 + m]);
    }
}

// =========================================================================
// K1: y[b,r,h,w] = sum_c f3t[r,c] x[b,c,h,w]   (y fp16)
// block: M=128 (r), N=256 (2 h-rows, contiguous in x), K=256, chunks of 16
// 512 threads, warps 4m x 4n, warp tile 32x64, 2-stage reg prefetch
// =========================================================================
__global__ __launch_bounds__(512, 1)
void k1_mma(const float* __restrict__ x) {
    __shared__ __half As[2][128 * A_LD];
    __shared__ __half Bs[2][16 * B1_LD];

    const int tid = threadIdx.x, wid = tid >> 5, lane = tid & 31;
    const int b = blockIdx.y, h0 = blockIdx.x * 2;
    const int wm = wid & 3, wn = wid >> 2;
    const float* xb = x + ((size_t)b * C_) * HW_ + (size_t)h0 * W_;

    float acc[2][8][4];
#pragma unroll
    for (int i = 0; i < 2; ++i)
#pragma unroll
        for (int j = 0; j < 8; ++j)
#pragma unroll
            for (int q = 0; q < 4; ++q) acc[i][j][q] = 0.f;

    const int am = tid >> 1, akh = (tid & 1) * 8;   // A loader (tid<256)
    const int bk = tid >> 5, bn8 = (tid & 31) * 8;  // B loader (all 512)

    // preload chunk 0
    {
        if (tid < 256)
            *(uint4*)&As[0][am * A_LD + akh] = *(const uint4*)&g_f3h[am * 256 + akh];
        float4 v0 = *(const float4*)(xb + (size_t)bk * HW_ + bn8);
        float4 v1 = *(const float4*)(xb + (size_t)bk * HW_ + bn8 + 4);
        __half2 p0 = __floats2half2_rn(v0.x, v0.y), p1 = __floats2half2_rn(v0.z, v0.w);
        __half2 p2 = __floats2half2_rn(v1.x, v1.y), p3 = __floats2half2_rn(v1.z, v1.w);
        uint4 w = make_uint4(*(uint32_t*)&p0, *(uint32_t*)&p1,
                             *(uint32_t*)&p2, *(uint32_t*)&p3);
        *(uint4*)&Bs[0][bk * B1_LD + bn8] = w;
    }
    __syncthreads();

    const uint32_t aBase = smem_u32(&As[0][0]);
    const uint32_t bBase = smem_u32(&Bs[0][0]);
    const int arow = wm * 32 + (lane & 15);
    const int acol = (lane >> 4) * 8;
    const int brow = (lane & 7) + ((lane >> 3) & 1) * 8;
    const int bcol = wn * 64 + ((lane >> 4) & 1) * 8;

    int cur = 0;
#pragma unroll 1
    for (int kc = 0; kc < 16; ++kc) {
        uint4 pa; float4 pb0, pb1;
        const bool more = (kc + 1) < 16;
        if (more) {
            int c0n = (kc + 1) * 16;
            if (tid < 256) pa = *(const uint4*)&g_f3h[am * 256 + c0n + akh];
            pb0 = *(const float4*)(xb + (size_t)(c0n + bk) * HW_ + bn8);
            pb1 = *(const float4*)(xb + (size_t)(c0n + bk) * HW_ + bn8 + 4);
        }

        uint32_t a[2][4];
        const uint32_t aS = aBase + cur * (128 * A_LD * 2);
#pragma unroll
        for (int mf = 0; mf < 2; ++mf)
            ldsm_x4(a[mf], aS + ((arow + mf * 16) * A_LD + acol) * 2);
        const uint32_t bS = bBase + cur * (16 * B1_LD * 2);
#pragma unroll
        for (int g = 0; g < 4; ++g) {
            uint32_t bf[4];
            ldsm_x4t(bf, bS + (brow * B1_LD + bcol + g * 16) * 2);
#pragma unroll
            for (int mf = 0; mf < 2; ++mf) {
                mma16816(acc[mf][g * 2 + 0], a[mf], bf + 0);
                mma16816(acc[mf][g * 2 + 1], a[mf], bf + 2);
            }
        }

        if (more) {
            int nxt = cur ^ 1;
            if (tid < 256) *(uint4*)&As[nxt][am * A_LD + akh] = pa;
            __half2 p0 = __floats2half2_rn(pb0.x, pb0.y), p1 = __floats2half2_rn(pb0.z, pb0.w);
            __half2 p2 = __floats2half2_rn(pb1.x, pb1.y), p3 = __floats2half2_rn(pb1.z, pb1.w);
            uint4 w = make_uint4(*(uint32_t*)&p0, *(uint32_t*)&p1,
                                 *(uint32_t*)&p2, *(uint32_t*)&p3);
            *(uint4*)&Bs[nxt][bk * B1_LD + bn8] = w;
            __syncthreads();
            cur = nxt;
        }
    }

    // epilogue: y fp16; two h-rows contiguous -> flat offset n
    const int r0 = wm * 32, n0 = wn * 64;
    const int lr = lane >> 2, lc = (lane & 3) * 2;
#pragma unroll
    for (int mf = 0; mf < 2; ++mf)
#pragma unroll
        for (int g = 0; g < 8; ++g) {
            int r = r0 + mf * 16 + lr;
            int n = n0 + g * 8 + lc;
            __half2 v0 = __floats2half2_rn(acc[mf][g][0], acc[mf][g][1]);
            __half2 v1 = __floats2half2_rn(acc[mf][g][2], acc[mf][g][3]);
            *(__half2*)(g_yh + (((size_t)b * R_ + r) * H_ + h0) * W_ + n) = v0;
            *(__half2*)(g_yh + (((size_t)b * R_ + r + 8) * H_ + h0) * W_ + n) = v1;
        }
}

// =========================================================================
// K2: separable depthwise, y fp16 -> z fp16, 8 outputs/thread, 16B stores
// =========================================================================
__global__ __launch_bounds__(256)
void k2_depthwise(const float* __restrict__ f1, const float* __restrict__ f2) {
    const int tid = threadIdx.x;
    const int qi = tid & 15, psub = tid >> 4;
    const int p = blockIdx.x * 16 + psub;
    const int r = blockIdx.y, b = blockIdx.z;
    if (p >= HP) return;

    const float w0 = f2[r], w1 = f2[128 + r], w2 = f2[256 + r];
    const float v0 = f1[r], v1 = f1[128 + r], v2 = f1[256 + r];

    const __half* yb = g_yh + ((((size_t)b * R_) + r) * H_ + p) * W_;
    const int q0 = qi * 8;

    float z[8];
#pragma unroll
    for (int j = 0; j < 8; ++j) z[j] = 0.f;

#pragma unroll
    for (int a = 0; a < 3; ++a) {
        const __half* row = yb + a * W_ + q0;
        float t[10];
        uint4 raw = *(const uint4*)row;
        __half2* hp = (__half2*)&raw;
#pragma unroll
        for (int j = 0; j < 4; ++j) {
            float2 f = __half22float2(hp[j]);
            t[j * 2] = f.x; t[j * 2 + 1] = f.y;
        }
        if (q0 < 120) {
            float2 f = __half22float2(*(const __half2*)(row + 8));
            t[8] = f.x; t[9] = f.y;
        } else { t[8] = 0.f; t[9] = 0.f; }
        const float va = (a == 0) ? v0 : ((a == 1) ? v1 : v2);
#pragma unroll
        for (int j = 0; j < 8; ++j)
            z[j] += va * (t[j] * w0 + t[j + 1] * w1 + t[j + 2] * w2);
    }
    if (q0 == 120) { z[6] = 0.f; z[7] = 0.f; }

    __half2 o0 = __floats2half2_rn(z[0], z[1]), o1 = __floats2half2_rn(z[2], z[3]);
    __half2 o2 = __floats2half2_rn(z[4], z[5]), o3 = __floats2half2_rn(z[6], z[7]);
    uint4 w = make_uint4(*(uint32_t*)&o0, *(uint32_t*)&o1,
                         *(uint32_t*)&o2, *(uint32_t*)&o3);
    *(uint4*)(g_zh + ((((size_t)b * R_) + r) * HP + p) * WPAD + q0) = w;
}

// =========================================================================
// K3: out[b,f,p,q] = sum_r f0[f,r] z[b,r,p,q]
// block: 128 threads, 4 warps (2m x 2n), warp tile 64x64, tile 128x128,
// K=128 chunks of 16, 3-stage cp.async. grid (126, 2 m-tiles, 32)
// Per chunk/warp: 4 A-ldsm + 4 B-ldsm -> 32 independent MMAs.
// =========================================================================
__global__ __launch_bounds__(128, 2)
void k3_mma(float* __restrict__ out) {
    __shared__ __half Asm[3][128 * A_LD];
    __shared__ __half Bsm[3][16 * B3_LD];

    const int tid = threadIdx.x, wid = tid >> 5, lane = tid & 31;
    const int p = blockIdx.x, m0 = blockIdx.y * 128, b = blockIdx.z;
    const int wm = wid & 1, wn = wid >> 1;
    const __half* zb = g_zh + ((size_t)b * R_ * HP + p) * WPAD;
    const size_t zks = (size_t)HP * WPAD;

    float acc[4][8][4];
#pragma unroll
    for (int i = 0; i < 4; ++i)
#pragma unroll
        for (int j = 0; j < 8; ++j)
#pragma unroll
            for (int q = 0; q < 4; ++q) acc[i][j][q] = 0.f;

    // loaders: A = 128 rows x 16 halves (2 segs/thread); B = 16 rows x 128
    const int br = tid >> 3, bs = (tid & 7) * 16;

#define K3_ISSUE(kc, st)                                                      \
    do {                                                                      \
        int k0_ = (kc) * 16;                                                  \
        cp_async16(smem_u32(&Asm[st][tid * A_LD + 0]),                        \
                   g_f0h + (size_t)(m0 + tid) * 128 + k0_);                   \
        cp_async16(smem_u32(&Asm[st][tid * A_LD + 8]),                        \
                   g_f0h + (size_t)(m0 + tid) * 128 + k0_ + 8);               \
        cp_async16(smem_u32(&Bsm[st][br * B3_LD + bs]),                       \
                   zb + (size_t)(k0_ + br) * zks + bs);                       \
        cp_async16(smem_u32(&Bsm[st][br * B3_LD + bs + 8]),                   \
                   zb + (size_t)(k0_ + br) * zks + bs + 8);                   \
        CP_COMMIT();                                                          \
    } while (0)

    K3_ISSUE(0, 0);
    K3_ISSUE(1, 1);

    const uint32_t aBase = smem_u32(&Asm[0][0]);
    const uint32_t bBase = smem_u32(&Bsm[0][0]);
    const int arow = wm * 64 + (lane & 15);
    const int acol = (lane >> 4) * 8;
    const int brow = (lane & 7) + ((lane >> 3) & 1) * 8;
    const int bcol = wn * 64 + ((lane >> 4) & 1) * 8;

#pragma unroll 1
    for (int kc = 0; kc < 8; ++kc) {
        if (kc < 7) CP_WAIT(1); else CP_WAIT(0);
        __syncthreads();
        if (kc + 2 < 8) K3_ISSUE(kc + 2, (kc + 2) % 3);

        const int s = kc % 3;
        // load ALL fragments first, then 32 independent MMAs
        uint32_t a[4][4];
        const uint32_t aS = aBase + s * (128 * A_LD * 2);
#pragma unroll
        for (int mf = 0; mf < 4; ++mf)
            ldsm_x4(a[mf], aS + ((arow + mf * 16) * A_LD + acol) * 2);
        uint32_t bf[4][4];
        const uint32_t bS = bBase + s * (16 * B3_LD * 2);
#pragma unroll
        for (int g2 = 0; g2 < 4; ++g2)
            ldsm_x4t(bf[g2], bS + (brow * B3_LD + bcol + g2 * 16) * 2);
#pragma unroll
        for (int g2 = 0; g2 < 4; ++g2)
#pragma unroll
            for (int mf = 0; mf < 4; ++mf) {
                mma16816(acc[mf][g2 * 2 + 0], a[mf], bf[g2] + 0);
                mma16816(acc[mf][g2 * 2 + 1], a[mf], bf[g2] + 2);
            }
    }

    // epilogue: out[b][f][p][q], skip q >= 126
    const int r0 = m0 + wm * 64, n0 = wn * 64;
    const int lr = lane >> 2, lc = (lane & 3) * 2;
#pragma unroll
    for (int mf = 0; mf < 4; ++mf)
#pragma unroll
        for (int g = 0; g < 8; ++g) {
            int f = r0 + mf * 16 + lr;
            int q = n0 + g * 8 + lc;
            if (q < WP) {
                float* d0 = out + (((size_t)(b * F_ + f)) * HP + p) * WP + q;
                *(float2*)d0 = make_float2(acc[mf][g][0], acc[mf][g][1]);
                float* d1 = out + (((size_t)(b * F_ + f + 8)) * HP + p) * WP + q;
                *(float2*)d1 = make_float2(acc[mf][g][2], acc[mf][g][3]);
            }
        }
}

extern "C" void kernel_launch(void* const* d_in, const int* in_sizes, int n_in,
                              void* d_out, int out_size) {
    const float* x  = (const float*)d_in[0];
    const float* f0 = (const float*)d_in[1];
    const float* f1 = (const float*)d_in[2];
    const float* f2 = (const float*)d_in[3];
    const float* f3 = (const float*)d_in[4];
    float* out = (float*)d_out;

    ksplit_weights<<<128, 256>>>(f0, f3);
    k1_mma<<<dim3(H_ / 2, B_), 512>>>(x);
    k2_depthwise<<<dim3(8, R_, B_), 256>>>(f1, f2);
    k3_mma<<<dim3(HP, 2, B_), 128>>>(out);
}

// round 10
// speedup vs baseline: 1.1337x; 1.0660x over previous
#include <cuda_runtime.h>
#include <cuda_fp16.h>
#include <cstdint>

#define B_   32
#define C_   256
#define H_   128
#define W_   128
#define R_   128
#define F_   256
#define HP   126
#define WP   126
#define WPAD 128
#define HW_  (H_ * W_)

// ---- device scratch (allocation-free) -----------------------------------
__device__ __half g_yh[(size_t)B_ * R_ * H_ * W_];     // fp16 134 MB
__device__ __half g_zh[(size_t)B_ * R_ * HP * WPAD];   // fp16 132 MB
__device__ __half g_f3h[128 * 256];                    // f3^T [r][c]
__device__ __half g_f0h[256 * 128];                    // f0   [f][r]

// ---- PTX helpers --------------------------------------------------------
__device__ __forceinline__ uint32_t smem_u32(const void* p) {
    uint32_t a;
    asm("{ .reg .u64 t; cvta.to.shared.u64 t, %1; cvt.u32.u64 %0, t; }"
        : "=r"(a) : "l"(p));
    return a;
}
__device__ __forceinline__ void ldsm_x4(uint32_t* r, uint32_t addr) {
    asm volatile("ldmatrix.sync.aligned.m8n8.x4.shared.b16 {%0,%1,%2,%3}, [%4];"
                 : "=r"(r[0]), "=r"(r[1]), "=r"(r[2]), "=r"(r[3]) : "r"(addr));
}
__device__ __forceinline__ void ldsm_x4t(uint32_t* r, uint32_t addr) {
    asm volatile("ldmatrix.sync.aligned.m8n8.x4.trans.shared.b16 {%0,%1,%2,%3}, [%4];"
                 : "=r"(r[0]), "=r"(r[1]), "=r"(r[2]), "=r"(r[3]) : "r"(addr));
}
__device__ __forceinline__ void mma16816(float* c, const uint32_t* a,
                                         const uint32_t* b) {
    asm volatile(
        "mma.sync.aligned.m16n8k16.row.col.f32.f16.f16.f32 "
        "{%0,%1,%2,%3}, {%4,%5,%6,%7}, {%8,%9}, {%0,%1,%2,%3};"
        : "+f"(c[0]), "+f"(c[1]), "+f"(c[2]), "+f"(c[3])
        : "r"(a[0]), "r"(a[1]), "r"(a[2]), "r"(a[3]), "r"(b[0]), "r"(b[1]));
}
__device__ __forceinline__ void cp_async16(uint32_t dst, const void* src) {
    asm volatile("{ .reg .u64 g; cvta.to.global.u64 g, %1;"
                 "  cp.async.cg.shared.global [%0], [g], 16; }"
                 :: "r"(dst), "l"(src) : "memory");
}
#define CP_COMMIT() asm volatile("cp.async.commit_group;" ::: "memory")
#define CP_WAIT(n)  asm volatile("cp.async.wait_group %0;" :: "n"(n) : "memory")

#define A_LD  24    // halves per A smem row (16 + 8 pad) -> 48B stride
#define B3_LD 136   // K3 B row: 128 + 8 pad halves
#define B1_LD 264   // K1 B row: 256 + 8 pad halves

#define DSMEM_BYTES 69632   // 68 KB dynamic smem (pipeline + staging overlay)

// =========================================================================
// Setup: f0 -> fp16 [f][r] ; f3 transpose -> fp16 [r][c]
// =========================================================================
__global__ void ksplit_weights(const float* __restrict__ f0,
                               const float* __restrict__ f3) {
    int i = blockIdx.x * 256 + threadIdx.x;
    if (i < 256 * 128) g_f0h[i] = __float2half_rn(f0[i]);
    if (i < 128 * 256) {
        int m = i >> 8, k = i & 255;
        g_f3h[m * 256 + k] = __float2half_rn(f3[k * 128 + m]);
    }
}

// =========================================================================
// K1: y[b,r,h,w] = sum_c f3t[r,c] x[b,c,h,w]   (y fp16)
// block: M=128 (r), N=256 (2 h-rows), K=256, chunks of 16
// 512 threads, warps 4m x 4n, warp tile 32x64, 2-stage reg prefetch
// Epilogue: stage y tile in smem, write 512B contiguous rows per warp.
// =========================================================================
__global__ __launch_bounds__(512, 1)
void k1_mma(const float* __restrict__ x) {
    extern __shared__ char dsm[];
    __half* Ah = (__half*)dsm;                 // 2 stages: 128*A_LD each
    __half* Bh = Ah + 2 * 128 * A_LD;          // 2 stages: 16*B1_LD each

    const int tid = threadIdx.x, wid = tid >> 5, lane = tid & 31;
    const int b = blockIdx.y, h0 = blockIdx.x * 2;
    const int wm = wid & 3, wn = wid >> 2;
    const float* xb = x + ((size_t)b * C_) * HW_ + (size_t)h0 * W_;

    float acc[2][8][4];
#pragma unroll
    for (int i = 0; i < 2; ++i)
#pragma unroll
        for (int j = 0; j < 8; ++j)
#pragma unroll
            for (int q = 0; q < 4; ++q) acc[i][j][q] = 0.f;

    const int am = tid >> 1, akh = (tid & 1) * 8;   // A loader (tid<256)
    const int bk = tid >> 5, bn8 = (tid & 31) * 8;  // B loader (all 512)

    // preload chunk 0
    {
        if (tid < 256)
            *(uint4*)&Ah[am * A_LD + akh] = *(const uint4*)&g_f3h[am * 256 + akh];
        float4 v0 = *(const float4*)(xb + (size_t)bk * HW_ + bn8);
        float4 v1 = *(const float4*)(xb + (size_t)bk * HW_ + bn8 + 4);
        __half2 p0 = __floats2half2_rn(v0.x, v0.y), p1 = __floats2half2_rn(v0.z, v0.w);
        __half2 p2 = __floats2half2_rn(v1.x, v1.y), p3 = __floats2half2_rn(v1.z, v1.w);
        uint4 w = make_uint4(*(uint32_t*)&p0, *(uint32_t*)&p1,
                             *(uint32_t*)&p2, *(uint32_t*)&p3);
        *(uint4*)&Bh[bk * B1_LD + bn8] = w;
    }
    __syncthreads();

    const uint32_t aBase = smem_u32(Ah);
    const uint32_t bBase = smem_u32(Bh);
    const int arow = wm * 32 + (lane & 15);
    const int acol = (lane >> 4) * 8;
    const int brow = (lane & 7) + ((lane >> 3) & 1) * 8;
    const int bcol = wn * 64 + ((lane >> 4) & 1) * 8;

    int cur = 0;
#pragma unroll 1
    for (int kc = 0; kc < 16; ++kc) {
        uint4 pa; float4 pb0, pb1;
        const bool more = (kc + 1) < 16;
        if (more) {
            int c0n = (kc + 1) * 16;
            if (tid < 256) pa = *(const uint4*)&g_f3h[am * 256 + c0n + akh];
            pb0 = *(const float4*)(xb + (size_t)(c0n + bk) * HW_ + bn8);
            pb1 = *(const float4*)(xb + (size_t)(c0n + bk) * HW_ + bn8 + 4);
        }

        uint32_t a[2][4];
        const uint32_t aS = aBase + cur * (128 * A_LD * 2);
#pragma unroll
        for (int mf = 0; mf < 2; ++mf)
            ldsm_x4(a[mf], aS + ((arow + mf * 16) * A_LD + acol) * 2);
        const uint32_t bS = bBase + cur * (16 * B1_LD * 2);
#pragma unroll
        for (int g = 0; g < 4; ++g) {
            uint32_t bf[4];
            ldsm_x4t(bf, bS + (brow * B1_LD + bcol + g * 16) * 2);
#pragma unroll
            for (int mf = 0; mf < 2; ++mf) {
                mma16816(acc[mf][g * 2 + 0], a[mf], bf + 0);
                mma16816(acc[mf][g * 2 + 1], a[mf], bf + 2);
            }
        }

        if (more) {
            int nxt = cur ^ 1;
            if (tid < 256) *(uint4*)&Ah[nxt * (128 * A_LD) + am * A_LD + akh] = pa;
            __half2 p0 = __floats2half2_rn(pb0.x, pb0.y), p1 = __floats2half2_rn(pb0.z, pb0.w);
            __half2 p2 = __floats2half2_rn(pb1.x, pb1.y), p3 = __floats2half2_rn(pb1.z, pb1.w);
            uint4 w = make_uint4(*(uint32_t*)&p0, *(uint32_t*)&p1,
                                 *(uint32_t*)&p2, *(uint32_t*)&p3);
            *(uint4*)&Bh[nxt * (16 * B1_LD) + bk * B1_LD + bn8] = w;
            __syncthreads();
            cur = nxt;
        }
    }

    // ---- epilogue: stage in smem (128 r-rows x 264 halves), then write ----
    __syncthreads();                      // pipeline smem no longer needed
    __half* sy = (__half*)dsm;            // 128*264*2 = 67584 B
    const int r0 = wm * 32, n0 = wn * 64;
    const int lr = lane >> 2, lc = (lane & 3) * 2;
#pragma unroll
    for (int mf = 0; mf < 2; ++mf)
#pragma unroll
        for (int g = 0; g < 8; ++g) {
            int r = r0 + mf * 16 + lr;
            int n = n0 + g * 8 + lc;
            __half2 v0 = __floats2half2_rn(acc[mf][g][0], acc[mf][g][1]);
            __half2 v1 = __floats2half2_rn(acc[mf][g][2], acc[mf][g][3]);
            *(__half2*)&sy[r * B1_LD + n] = v0;
            *(__half2*)&sy[(r + 8) * B1_LD + n] = v1;
        }
    __syncthreads();
    // each warp writes 8 full r-rows (512B contiguous each)
#pragma unroll
    for (int i = 0; i < 8; ++i) {
        int r = wid * 8 + i;
        uint4 v = *(const uint4*)&sy[r * B1_LD + lane * 8];
        *(uint4*)(g_yh + (((size_t)b * R_ + r) * H_ + h0) * W_ + lane * 8) = v;
    }
}

// =========================================================================
// K2: separable depthwise, y fp16 -> z fp16, 8 outputs/thread, 16B stores
// =========================================================================
__global__ __launch_bounds__(256)
void k2_depthwise(const float* __restrict__ f1, const float* __restrict__ f2) {
    const int tid = threadIdx.x;
    const int qi = tid & 15, psub = tid >> 4;
    const int p = blockIdx.x * 16 + psub;
    const int r = blockIdx.y, b = blockIdx.z;
    if (p >= HP) return;

    const float w0 = f2[r], w1 = f2[128 + r], w2 = f2[256 + r];
    const float v0 = f1[r], v1 = f1[128 + r], v2 = f1[256 + r];

    const __half* yb = g_yh + ((((size_t)b * R_) + r) * H_ + p) * W_;
    const int q0 = qi * 8;

    float z[8];
#pragma unroll
    for (int j = 0; j < 8; ++j) z[j] = 0.f;

#pragma unroll
    for (int a = 0; a < 3; ++a) {
        const __half* row = yb + a * W_ + q0;
        float t[10];
        uint4 raw = *(const uint4*)row;
        __half2* hp = (__half2*)&raw;
#pragma unroll
        for (int j = 0; j < 4; ++j) {
            float2 f = __half22float2(hp[j]);
            t[j * 2] = f.x; t[j * 2 + 1] = f.y;
        }
        if (q0 < 120) {
            float2 f = __half22float2(*(const __half2*)(row + 8));
            t[8] = f.x; t[9] = f.y;
        } else { t[8] = 0.f; t[9] = 0.f; }
        const float va = (a == 0) ? v0 : ((a == 1) ? v1 : v2);
#pragma unroll
        for (int j = 0; j < 8; ++j)
            z[j] += va * (t[j] * w0 + t[j + 1] * w1 + t[j + 2] * w2);
    }
    if (q0 == 120) { z[6] = 0.f; z[7] = 0.f; }

    __half2 o0 = __floats2half2_rn(z[0], z[1]), o1 = __floats2half2_rn(z[2], z[3]);
    __half2 o2 = __floats2half2_rn(z[4], z[5]), o3 = __floats2half2_rn(z[6], z[7]);
    uint4 w = make_uint4(*(uint32_t*)&o0, *(uint32_t*)&o1,
                         *(uint32_t*)&o2, *(uint32_t*)&o3);
    *(uint4*)(g_zh + ((((size_t)b * R_) + r) * HP + p) * WPAD + q0) = w;
}

// =========================================================================
// K3: out[b,f,p,q] = sum_r f0[f,r] z[b,r,p,q]
// block: 256 threads, warps 4m x 2n, warp tile 32x64, tile 128x128,
// K=128 chunks of 16, 3-stage cp.async.
// Epilogue: stage fp32 tile in smem (rows padded to 132 floats),
// then linear float2 writes -> 504B contiguous per f-row.
// =========================================================================
#define ST_LD 132   // floats per staged output row

__global__ __launch_bounds__(256, 2)
void k3_mma(float* __restrict__ out) {
    extern __shared__ char dsm[];
    __half* Asm = (__half*)dsm;                 // 3 stages: 128*A_LD
    __half* Bsm = Asm + 3 * 128 * A_LD;         // 3 stages: 16*B3_LD

    const int tid = threadIdx.x, wid = tid >> 5, lane = tid & 31;
    const int p = blockIdx.x, m0 = blockIdx.y * 128, b = blockIdx.z;
    const int wm = wid & 3, wn = wid >> 2;
    const __half* zb = g_zh + ((size_t)b * R_ * HP + p) * WPAD;
    const size_t zks = (size_t)HP * WPAD;

    float acc[2][8][4];
#pragma unroll
    for (int i = 0; i < 2; ++i)
#pragma unroll
        for (int j = 0; j < 8; ++j)
#pragma unroll
            for (int q = 0; q < 4; ++q) acc[i][j][q] = 0.f;

    const int ar = tid >> 1, asg = (tid & 1) * 8;
    const int br = tid >> 4, bsg = (tid & 15) * 8;

#define K3_ISSUE(kc, st)                                                      \
    do {                                                                      \
        int k0_ = (kc) * 16;                                                  \
        cp_async16(smem_u32(&Asm[(st) * (128 * A_LD) + ar * A_LD + asg]),     \
                   g_f0h + (size_t)(m0 + ar) * 128 + k0_ + asg);              \
        cp_async16(smem_u32(&Bsm[(st) * (16 * B3_LD) + br * B3_LD + bsg]),    \
                   zb + (size_t)(k0_ + br) * zks + bsg);                      \
        CP_COMMIT();                                                          \
    } while (0)

    K3_ISSUE(0, 0);
    K3_ISSUE(1, 1);

    const uint32_t aBase = smem_u32(Asm);
    const uint32_t bBase = smem_u32(Bsm);
    const int arow = wm * 32 + (lane & 15);
    const int acol = (lane >> 4) * 8;
    const int brow = (lane & 7) + ((lane >> 3) & 1) * 8;
    const int bcol = wn * 64 + ((lane >> 4) & 1) * 8;

#pragma unroll 1
    for (int kc = 0; kc < 8; ++kc) {
        if (kc < 7) CP_WAIT(1); else CP_WAIT(0);
        __syncthreads();
        if (kc + 2 < 8) K3_ISSUE(kc + 2, (kc + 2) % 3);

        const int s = kc % 3;
        uint32_t a[2][4];
        const uint32_t aS = aBase + s * (128 * A_LD * 2);
#pragma unroll
        for (int mf = 0; mf < 2; ++mf)
            ldsm_x4(a[mf], aS + ((arow + mf * 16) * A_LD + acol) * 2);
        const uint32_t bS = bBase + s * (16 * B3_LD * 2);
#pragma unroll
        for (int g = 0; g < 4; ++g) {
            uint32_t bf[4];
            ldsm_x4t(bf, bS + (brow * B3_LD + bcol + g * 16) * 2);
#pragma unroll
            for (int mf = 0; mf < 2; ++mf) {
                mma16816(acc[mf][g * 2 + 0], a[mf], bf + 0);
                mma16816(acc[mf][g * 2 + 1], a[mf], bf + 2);
            }
        }
    }

    // ---- epilogue: stage tile (128 f x 128 q fp32), then contiguous rows --
    __syncthreads();                      // pipeline smem no longer needed
    float* st = (float*)dsm;              // 128*ST_LD*4 = 67584 B
    const int r0 = wm * 32, n0 = wn * 64;
    const int lr = lane >> 2, lc = (lane & 3) * 2;
#pragma unroll
    for (int mf = 0; mf < 2; ++mf)
#pragma unroll
        for (int g = 0; g < 8; ++g) {
            int f = r0 + mf * 16 + lr;
            int q = n0 + g * 8 + lc;
            *(float2*)&st[f * ST_LD + q] = make_float2(acc[mf][g][0], acc[mf][g][1]);
            *(float2*)&st[(f + 8) * ST_LD + q] = make_float2(acc[mf][g][2], acc[mf][g][3]);
        }
    __syncthreads();
    // linear copy: 128 rows x 63 float2 (126 floats), fully coalesced
    {
        float* obase = out + ((size_t)(b * F_) + m0) * (HP * WP) + (size_t)p * WP;
        int row = tid / 63, col = tid - row * 63;
#pragma unroll 1
        for (int e = tid; e < 128 * 63; e += 256) {
            float2 v = *(const float2*)&st[row * ST_LD + col * 2];
            *(float2*)(obase + (size_t)row * (HP * WP) + col * 2) = v;
            col += 4; row += 4;
            if (col >= 63) { col -= 63; row += 1; }
        }
    }
}

extern "C" void kernel_launch(void* const* d_in, const int* in_sizes, int n_in,
                              void* d_out, int out_size) {
    const float* x  = (const float*)d_in[0];
    const float* f0 = (const float*)d_in[1];
    const float* f1 = (const float*)d_in[2];
    const float* f2 = (const float*)d_in[3];
    const float* f3 = (const float*)d_in[4];
    float* out = (float*)d_out;

    cudaFuncSetAttribute(k1_mma, cudaFuncAttributeMaxDynamicSharedMemorySize,
                         DSMEM_BYTES);
    cudaFuncSetAttribute(k3_mma, cudaFuncAttributeMaxDynamicSharedMemorySize,
                         DSMEM_BYTES);

    ksplit_weights<<<128, 256>>>(f0, f3);
    k1_mma<<<dim3(H_ / 2, B_), 512, DSMEM_BYTES>>>(x);
    k2_depthwise<<<dim3(8, R_, B_), 256>>>(f1, f2);
    k3_mma<<<dim3(HP, 2, B_), 256, DSMEM_BYTES>>>(out);
}